// round 15
// baseline (speedup 1.0000x reference)
#include <cuda_runtime.h>
#include <cstdint>
#include <math.h>

#define DIM      128
#define NPARAMS  8384
#define NT       256            // 8 warps

// Triangular k-interleaved L layout. 16-row group g stores 16(g+1) data
// cols at stride GS(g) = 32*(g>>1)+56 (≡ 24 mod 32, >= data+16), base
// GB(g) (≡ 0 mod 32), plus +16 float skew when (r&4). Closed forms:
//   h = g>>1;  GS = 32h+56
//   GB = 512h^2 + 1280h + (g&1 ? 512h+896 : 0)
// Within each 8-col k-group, logical order [k0,k4,k1,k5,k2,k6,k3,k7]
// -> fragment pair (k+tg, k+tg+4) is one LDS.64 at phys offset 2*tg.
#define OFF_EPS  13312          // eps, tf32, k-interleaved, 128
#define OFF_LD   13440          // log-diag, 128
#define OFF_MEAN 13568
#define OFF_DIAG 13696
#define SMEM_FLOATS 13824       // 55296 B -> 4 CTAs/SM

// Work items: bit6 = pair (tiles (mt,nt),(mt+1,nt)), bits5:3 = mt, bits2:0 = nt.
__constant__ uint8_t TILE_TAB[8][6] = {
    {0x76, 0x40, 0xFF, 0xFF, 0xFF, 0xFF},
    {0x6D, 0x49, 0xFF, 0xFF, 0xFF, 0xFF},
    {0x64, 0x52, 0xFF, 0xFF, 0xFF, 0xFF},
    {0x74, 0x62, 0xFF, 0xFF, 0xFF, 0xFF},
    {0x5B, 0x3D, 0xFF, 0xFF, 0xFF, 0xFF},
    {0x6B, 0x72, 0xFF, 0xFF, 0xFF, 0xFF},
    {0x3F, 0x3B, 0x50, 0xFF, 0xFF, 0xFF},
    {0x59, 0x69, 0x39, 0x60, 0x70, 0xFF},
};

__device__ __forceinline__ int rowbase(int r) {
    const int h = r >> 5;                       // group pair
    const int gs = 32 * h + 56;                 // stride of r's group
    int base = (512 * h + 1280) * h;            // even-group base
    if (r & 16) base += 512 * h + 896;          // odd group within pair
    return base + (r & 15) * gs + ((r & 4) << 2);
}

__device__ __forceinline__ void mma_tf32(float* d, uint32_t a0, uint32_t a1,
                                         uint32_t a2, uint32_t a3,
                                         uint32_t b0, uint32_t b1) {
    asm volatile(
        "mma.sync.aligned.m16n8k8.row.col.f32.tf32.tf32.f32 "
        "{%0,%1,%2,%3}, {%4,%5,%6,%7}, {%8,%9}, {%0,%1,%2,%3};"
        : "+f"(d[0]), "+f"(d[1]), "+f"(d[2]), "+f"(d[3])
        : "r"(a0), "r"(a1), "r"(a2), "r"(a3), "r"(b0), "r"(b1));
}

__device__ __forceinline__ uint32_t to_tf32(float v) {
    uint32_t t;
    asm("cvt.rna.tf32.f32 %0, %1;" : "=r"(t) : "f"(v));
    return t;
}

// Transform 4 logical cols j0..j0+3 of row r (scale/exp/zero); save log-diag.
__device__ __forceinline__ float4 xform4(float* smf, int r, int j0,
                                         float rw, float4 v) {
    if (j0 + 3 < r) {
        v.x *= rw; v.y *= rw; v.z *= rw; v.w *= rw;
    } else {
        float vv[4] = {v.x, v.y, v.z, v.w};
        #pragma unroll
        for (int e = 0; e < 4; e++) {
            int j = j0 + e;
            float raw = vv[e];
            if (j < r)       vv[e] = raw * rw;
            else if (j == r) { smf[OFF_LD + r] = raw; vv[e] = expf(raw); }
            else             vv[e] = 0.0f;
        }
        v = make_float4(vv[0], vv[1], vv[2], vv[3]);
    }
    return v;
}

// Process one 8-col chunk of row r: transform + interleave-pack + 2x STS.128.
__device__ __forceinline__ void chunk_store(float* smf, const float* P,
                                            int r, int j0, float rw) {
    float4 lo = make_float4(0.f, 0.f, 0.f, 0.f);
    float4 hi = make_float4(0.f, 0.f, 0.f, 0.f);
    if (j0 <= r) {
        if (r < 64) {
            lo = *(const float4*)(P + 256 + 128 * r + j0);
            hi = *(const float4*)(P + 256 + 128 * r + j0 + 4);
        } else {
            float4 a = *(const float4*)(P + 16508 - 128 * r - j0);
            float4 b = *(const float4*)(P + 16504 - 128 * r - j0);
            lo = make_float4(a.w, a.z, a.y, a.x);
            hi = make_float4(b.w, b.z, b.y, b.x);
        }
        lo = xform4(smf, r, j0, rw, lo);
        hi = xform4(smf, r, j0 + 4, rw, hi);
    }
    const int rb = rowbase(r) + j0;
    *(uint4*)&smf[rb] = make_uint4(to_tf32(lo.x), to_tf32(hi.x),
                                   to_tf32(lo.y), to_tf32(hi.y));
    *(uint4*)&smf[rb + 4] = make_uint4(to_tf32(lo.z), to_tf32(hi.z),
                                       to_tf32(lo.w), to_tf32(hi.w));
}

// Old-layout off-diagonal store (direct float2 + xor4 mirror) for the
// second sub-tile of diag-lead pairs.
__device__ __forceinline__ void store_old_offdiag(char* SgB, const float d[2][4],
                                                  int m0, int n0, int gr, int tg) {
    const uint32_t rb = (uint32_t)(m0 + gr) * (DIM * 4);
    #pragma unroll
    for (int s = 0; s < 2; s++) {
        const uint32_t co = (uint32_t)(n0 + 8 * s + 2 * tg) * 4;
        *(float2*)(SgB + rb + co)               = make_float2(d[s][0], d[s][1]);
        *(float2*)(SgB + rb + 8 * DIM * 4 + co) = make_float2(d[s][2], d[s][3]);
    }
    const int odd  = gr & 1;
    const uint32_t ct = (uint32_t)(m0 + (gr & ~1)) * 4;
    #pragma unroll
    for (int s = 0; s < 2; s++) {
        float q0 = __shfl_xor_sync(0xffffffffu, d[s][0], 4);
        float q1 = __shfl_xor_sync(0xffffffffu, d[s][1], 4);
        float q2 = __shfl_xor_sync(0xffffffffu, d[s][2], 4);
        float q3 = __shfl_xor_sync(0xffffffffu, d[s][3], 4);
        const uint32_t rt = (uint32_t)(n0 + 8 * s + 2 * tg + odd) * (DIM * 4);
        float2 w0 = odd ? make_float2(q1, d[s][1]) : make_float2(d[s][0], q0);
        float2 w1 = odd ? make_float2(q3, d[s][3]) : make_float2(d[s][2], q2);
        *(float2*)(SgB + rt + ct)      = w0;
        *(float2*)(SgB + rt + ct + 32) = w1;
    }
}

// Permuted-layout store: 2x STG.128 direct + 8x scalar mirror
// (base + constant offsets).
__device__ __forceinline__ void store_perm(char* SgB, const float d[2][4],
                                           int m0, int n0, int gr, int tg) {
    const uint32_t co = (uint32_t)(n0 + 4 * tg) * 4;
    *(float4*)(SgB + (uint32_t)(m0 + gr) * (DIM * 4) + co) =
        make_float4(d[0][0], d[0][1], d[1][0], d[1][1]);
    *(float4*)(SgB + (uint32_t)(m0 + 8 + gr) * (DIM * 4) + co) =
        make_float4(d[0][2], d[0][3], d[1][2], d[1][3]);
    // mirror: rows n0+4tg+{0..3}, cols m0+gr and m0+gr+8
    char* mb = SgB + (uint32_t)(n0 + 4 * tg) * (DIM * 4)
                   + (uint32_t)(m0 + gr) * 4;
    *(float*)(mb)                    = d[0][0];
    *(float*)(mb + 512)              = d[0][1];
    *(float*)(mb + 1024)             = d[1][0];
    *(float*)(mb + 1536)             = d[1][1];
    *(float*)(mb + 32)               = d[0][2];
    *(float*)(mb + 512 + 32)         = d[0][3];
    *(float*)(mb + 1024 + 32)        = d[1][2];
    *(float*)(mb + 1536 + 32)        = d[1][3];
}

__global__ __launch_bounds__(NT, 4)
void fld_mma_kernel(const float* __restrict__ params,
                    const float* __restrict__ eps,
                    float* __restrict__ sample,
                    float* __restrict__ kl,
                    float* __restrict__ sigma)
{
    extern __shared__ float smf[];

    const int b   = blockIdx.x;
    const int tid = threadIdx.x;
    const int wid = tid >> 5;
    const int lid = tid & 31;
    const int gr  = lid >> 2;
    const int tg  = lid & 3;
    const float* P = params + (size_t)b * NPARAMS;

    // ---- phase 0: mean, eps (tf32, k-interleaved) ----
    if (tid < DIM) {
        smf[OFF_MEAN + tid] = P[tid];
        const int lo3 = tid & 7;
        const int phys = (tid & ~7) | ((lo3 < 4) ? (lo3 << 1) : (((lo3 - 4) << 1) | 1));
        *(uint32_t*)&smf[OFF_EPS + phys] = to_tf32(eps[(size_t)b * DIM + tid]);
    }

    // ---- phase 1: coalesced triangular unpack (8-col chunks) ----
    #pragma unroll
    for (int q = 0; q < 4; q++) {
        const int r  = 64 + wid + 8 * q + 32 * (lid >> 4);
        const int j0 = (lid & 15) << 3;
        if (j0 < (r & ~15) + 16) {
            const float rw = rsqrtf((float)(r + 1));
            chunk_store(smf, P, r, j0, rw);
        }
    }
    #pragma unroll
    for (int q = 0; q < 2; q++) {
        const int base = wid * 4 + (lid >> 3);
        const int r  = q ? (63 - base) : base;
        const int j0 = (lid & 7) << 3;
        if (j0 < (r & ~15) + 16) {
            const float rw = rsqrtf((float)(r + 1));
            chunk_store(smf, P, r, j0, rw);
        }
    }
    __syncthreads();

    // ---- phase 2: m32n16 paired / single tiles; sample fused into diag ----
    char* SgB = (char*)(sigma + (size_t)b * DIM * DIM);

    for (int t = 0; t < 6; t++) {
        const uint32_t code = TILE_TAB[wid][t];
        if (code == 0xFF) break;
        const bool pair = (code & 0x40) != 0;
        const int mt0 = (code >> 3) & 7;
        const int nt  = code & 7;
        const int n0  = nt * 16;
        const int m0a = mt0 * 16;
        const bool alias = (mt0 == nt);
        const int ksteps = 2 * (nt + 1);

        const int ar0 = rowbase(m0a + gr) + 2 * tg;
        const int ar1 = rowbase(m0a + 8 + gr) + 2 * tg;
        const int cr0 = rowbase(((m0a + 16) & 127) + gr) + 2 * tg;
        const int cr1 = rowbase(((m0a + 24) & 127) + gr) + 2 * tg;

        float d0[2][4], d1[2][4];
        #pragma unroll
        for (int s = 0; s < 2; s++)
            #pragma unroll
            for (int c = 0; c < 4; c++) { d0[s][c] = 0.0f; d1[s][c] = 0.0f; }

        if (alias) {
            // diag-lead: B aliases A; fused eps column for sample.
            // Eps fragment loaded by ALL lanes (same addr -> broadcast);
            // lanes gr != 0 feed output cols 1-7 of `de`, which are unread.
            float de[4] = {0.f, 0.f, 0.f, 0.f};
            #pragma unroll 2
            for (int ks = 0; ks < ksteps; ks++) {
                const int k0 = ks * 8;
                uint2 A0 = *(const uint2*)&smf[ar0 + k0];   // (a0, a2)
                uint2 A1 = *(const uint2*)&smf[ar1 + k0];   // (a1, a3)
                mma_tf32(d0[0], A0.x, A1.x, A0.y, A1.y, A0.x, A0.y);
                mma_tf32(d0[1], A0.x, A1.x, A0.y, A1.y, A1.x, A1.y);
                uint2 E = *(const uint2*)&smf[OFF_EPS + k0 + 2 * tg];
                mma_tf32(de, A0.x, A1.x, A0.y, A1.y, E.x, E.y);
                if (pair) {
                    uint2 C0 = *(const uint2*)&smf[cr0 + k0];
                    uint2 C1 = *(const uint2*)&smf[cr1 + k0];
                    mma_tf32(d1[0], C0.x, C1.x, C0.y, C1.y, A0.x, A0.y);
                    mma_tf32(d1[1], C0.x, C1.x, C0.y, C1.y, A1.x, A1.y);
                }
            }
            if (tg == 0) {
                sample[(size_t)b * DIM + m0a + gr] =
                    smf[OFF_MEAN + m0a + gr] + de[0];
                sample[(size_t)b * DIM + m0a + 8 + gr] =
                    smf[OFF_MEAN + m0a + 8 + gr] + de[2];
            }
            {
                const uint32_t rb = (uint32_t)(m0a + gr) * (DIM * 4);
                #pragma unroll
                for (int s = 0; s < 2; s++) {
                    const uint32_t co = (uint32_t)(n0 + 8 * s + 2 * tg) * 4;
                    *(float2*)(SgB + rb + co) =
                        make_float2(d0[s][0], d0[s][1]);
                    *(float2*)(SgB + rb + 8 * DIM * 4 + co) =
                        make_float2(d0[s][2], d0[s][3]);
                }
                if (2 * tg == (gr & ~1)) {
                    int c = gr & 1;
                    smf[OFF_DIAG + m0a + gr]     = d0[0][c];
                    smf[OFF_DIAG + m0a + gr + 8] = d0[1][2 + c];
                }
            }
            if (pair)
                store_old_offdiag(SgB, d1, m0a + 16, n0, gr, tg);
        } else {
            // permuted B rows -> thread owns 4 consecutive output columns
            const int pg  = ((gr >> 1) << 2) | (gr & 1);
            const int br0 = rowbase(n0 + pg) + 2 * tg;
            const int br1 = rowbase(n0 + pg + 2) + 2 * tg;
            #pragma unroll 2
            for (int ks = 0; ks < ksteps; ks++) {
                const int k0 = ks * 8;
                uint2 A0 = *(const uint2*)&smf[ar0 + k0];
                uint2 A1 = *(const uint2*)&smf[ar1 + k0];
                uint2 B0 = *(const uint2*)&smf[br0 + k0];
                uint2 B1 = *(const uint2*)&smf[br1 + k0];
                mma_tf32(d0[0], A0.x, A1.x, A0.y, A1.y, B0.x, B0.y);
                mma_tf32(d0[1], A0.x, A1.x, A0.y, A1.y, B1.x, B1.y);
                if (pair) {
                    uint2 C0 = *(const uint2*)&smf[cr0 + k0];
                    uint2 C1 = *(const uint2*)&smf[cr1 + k0];
                    mma_tf32(d1[0], C0.x, C1.x, C0.y, C1.y, B0.x, B0.y);
                    mma_tf32(d1[1], C0.x, C1.x, C0.y, C1.y, B1.x, B1.y);
                }
            }
            store_perm(SgB, d0, m0a, n0, gr, tg);
            if (pair)
                store_perm(SgB, d1, m0a + 16, n0, gr, tg);
        }
    }
    __syncthreads();   // OFF_DIAG / OFF_LD complete

    // ---- phase 3: kl (warp 0) ----
    if (wid == 0) {
        float t = 0.0f;
        #pragma unroll
        for (int k = 0; k < 4; k++) {
            int rr = lid + 32 * k;
            float m = smf[OFF_MEAN + rr];
            t += smf[OFF_DIAG + rr] - 1.0f + m * m - 2.0f * smf[OFF_LD + rr];
        }
        #pragma unroll
        for (int o = 16; o > 0; o >>= 1)
            t += __shfl_down_sync(0xffffffffu, t, o);
        if (lid == 0) kl[b] = 0.5f * t;
    }
}

extern "C" void kernel_launch(void* const* d_in, const int* in_sizes, int n_in,
                              void* d_out, int out_size)
{
    const float* params = (const float*)d_in[0];
    const float* eps    = (const float*)d_in[1];
    const int B = in_sizes[0] / NPARAMS;

    float* out    = (float*)d_out;
    float* sample = out;                       // B * 128
    float* kl     = out + (size_t)B * DIM;     // B
    float* sigma  = kl + B;                    // B * 128 * 128

    const int smem = SMEM_FLOATS * sizeof(float);
    cudaFuncSetAttribute(fld_mma_kernel,
                         cudaFuncAttributeMaxDynamicSharedMemorySize, smem);
    fld_mma_kernel<<<B, NT, smem>>>(params, eps, sample, kl, sigma);
}